// round 11
// baseline (speedup 1.0000x reference)
#include <cuda_runtime.h>
#include <math.h>

#define T_STEPS 512
#define BATCH   64
#define IN_DIM  512
#define RNN_DIM 512

#define NCTA2   128   // 32 jblk x 4 bblk
#define NTHR2   256
#define GRP_SZ  32

typedef unsigned long long ull;

// scratch (no device allocs allowed)
__device__ float g_pre[(size_t)T_STEPS * BATCH * RNN_DIM];   // 64MB
__device__ float g_hT[2][RNN_DIM * BATCH];                    // [parity][r][b]
__device__ ull g_grp[4 * 16];                                 // group ctrs, 128B apart

// ---------------------------------------------------------------------------
// Phase 1: pre = X @ Wx + bias. 128x128x16 register-tiled fp32 GEMM,
// double-buffered smem (one __syncthreads per K-tile, loads overlapped).
// Block (0,0) resets phase-2 barrier state (stream-ordered -> race-free).
// ---------------------------------------------------------------------------
#define BM 128
#define BN 128
#define BK 16
#define NKT (IN_DIM / BK)   // 32 K-tiles

__global__ __launch_bounds__(256) void gemm_pre_kernel(
    const float* __restrict__ X,
    const float* __restrict__ W,
    const float* __restrict__ bias)
{
    if (blockIdx.x == 0 && blockIdx.y == 0 && threadIdx.x < 4)
        g_grp[threadIdx.x * 16] = 0ULL;

    __shared__ float As[2][BK][BM];   // 16KB
    __shared__ float Bs[2][BK][BN];   // 16KB

    const int tid = threadIdx.x;
    const int bm = blockIdx.x;
    const int bn = blockIdx.y;

    const float* Aptr = X + (size_t)bm * BM * IN_DIM;
    const float* Bptr = W + (size_t)bn * BN;

    const int tm = (tid / 16) * 8;
    const int tn = (tid % 16) * 8;

    // load assignments (each thread: 2 float4 of A, 2 float4 of B per tile)
    const int a_row = tid >> 1;            // 0..127
    const int a_k0  = (tid & 1) * 4;       // 0 or 4 (second quad at +8)
    const int b_k   = tid >> 5;            // 0..7   (second row at +8)
    const int b_nq  = (tid & 31) * 4;      // 0..124

    float c[8][8];
    #pragma unroll
    for (int i = 0; i < 8; i++)
        #pragma unroll
        for (int j = 0; j < 8; j++)
            c[i][j] = 0.0f;

    // prologue: load tile 0 into buffer 0
    float4 av0 = *(const float4*)(Aptr + (size_t)a_row * IN_DIM + a_k0);
    float4 av1 = *(const float4*)(Aptr + (size_t)a_row * IN_DIM + a_k0 + 8);
    float4 bv0 = *(const float4*)(Bptr + (size_t)b_k * RNN_DIM + b_nq);
    float4 bv1 = *(const float4*)(Bptr + (size_t)(b_k + 8) * RNN_DIM + b_nq);
    As[0][a_k0 + 0][a_row] = av0.x;
    As[0][a_k0 + 1][a_row] = av0.y;
    As[0][a_k0 + 2][a_row] = av0.z;
    As[0][a_k0 + 3][a_row] = av0.w;
    As[0][a_k0 + 8][a_row] = av1.x;
    As[0][a_k0 + 9][a_row] = av1.y;
    As[0][a_k0 + 10][a_row] = av1.z;
    As[0][a_k0 + 11][a_row] = av1.w;
    *(float4*)&Bs[0][b_k][b_nq] = bv0;
    *(float4*)&Bs[0][b_k + 8][b_nq] = bv1;
    __syncthreads();

    for (int kt = 0; kt < NKT; kt++) {
        const int cur = kt & 1;
        const int nxt = cur ^ 1;

        // issue next tile's loads (in flight during compute)
        if (kt < NKT - 1) {
            int k0 = (kt + 1) * BK;
            av0 = *(const float4*)(Aptr + (size_t)a_row * IN_DIM + k0 + a_k0);
            av1 = *(const float4*)(Aptr + (size_t)a_row * IN_DIM + k0 + a_k0 + 8);
            bv0 = *(const float4*)(Bptr + (size_t)(k0 + b_k) * RNN_DIM + b_nq);
            bv1 = *(const float4*)(Bptr + (size_t)(k0 + b_k + 8) * RNN_DIM + b_nq);
        }

        // compute current tile
        #pragma unroll
        for (int k = 0; k < BK; k++) {
            float ar[8], br[8];
            *(float4*)(ar)     = *(float4*)&As[cur][k][tm];
            *(float4*)(ar + 4) = *(float4*)&As[cur][k][tm + 4];
            *(float4*)(br)     = *(float4*)&Bs[cur][k][tn];
            *(float4*)(br + 4) = *(float4*)&Bs[cur][k][tn + 4];
            #pragma unroll
            for (int i = 0; i < 8; i++)
                #pragma unroll
                for (int j = 0; j < 8; j++)
                    c[i][j] += ar[i] * br[j];
        }

        // stage next tile; single sync per tile
        if (kt < NKT - 1) {
            As[nxt][a_k0 + 0][a_row] = av0.x;
            As[nxt][a_k0 + 1][a_row] = av0.y;
            As[nxt][a_k0 + 2][a_row] = av0.z;
            As[nxt][a_k0 + 3][a_row] = av0.w;
            As[nxt][a_k0 + 8][a_row] = av1.x;
            As[nxt][a_k0 + 9][a_row] = av1.y;
            As[nxt][a_k0 + 10][a_row] = av1.z;
            As[nxt][a_k0 + 11][a_row] = av1.w;
            *(float4*)&Bs[nxt][b_k][b_nq] = bv0;
            *(float4*)&Bs[nxt][b_k + 8][b_nq] = bv1;
            __syncthreads();
        }
    }

    float4 bb0 = *(const float4*)(bias + bn * BN + tn);
    float4 bb1 = *(const float4*)(bias + bn * BN + tn + 4);
    #pragma unroll
    for (int i = 0; i < 8; i++) {
        size_t row = (size_t)bm * BM + tm + i;
        float4 v0, v1;
        v0.x = c[i][0] + bb0.x; v0.y = c[i][1] + bb0.y;
        v0.z = c[i][2] + bb0.z; v0.w = c[i][3] + bb0.w;
        v1.x = c[i][4] + bb1.x; v1.y = c[i][5] + bb1.y;
        v1.z = c[i][6] + bb1.z; v1.w = c[i][7] + bb1.w;
        *(float4*)(g_pre + row * RNN_DIM + bn * BN + tn)     = v0;
        *(float4*)(g_pre + row * RNN_DIM + bn * BN + tn + 4) = v1;
    }
}

// ---------------------------------------------------------------------------
// Phase 2: persistent RNN — R4 structure, split arrive/wait barrier
// (out-store + pre-prefetch between them). Unchanged from R10.
// ---------------------------------------------------------------------------
__device__ __forceinline__ void group_arrive(int grp)
{
    __syncthreads();                     // all g_hT stores issued
    if (threadIdx.x == 0) {
        __threadfence();
        atomicAdd(&g_grp[grp * 16], 1ULL);   // no-return -> REDG
    }
}
__device__ __forceinline__ void group_wait(int grp, ull step)
{
    if (threadIdx.x == 0) {
        volatile ull* ctr = (volatile ull*)&g_grp[grp * 16];
        ull need = (ull)GRP_SZ * step;
        while (*ctr < need) { }
        __threadfence();
    }
    __syncthreads();
}

extern __shared__ float smem2[];

__global__ __launch_bounds__(NTHR2) void rnn_seq_kernel(
    const float* __restrict__ W,
    const float* __restrict__ init_hidden,
    float* __restrict__ out)
{
    float* ws = smem2;                 // [512][16] Wh slice, 32KB
    float* hs = smem2 + RNN_DIM * 16;  // [512][16] h slab, 32KB (rows<256 = red)

    const int tid  = threadIdx.x;
    const int jblk = blockIdx.x & 31;
    const int bblk = blockIdx.x >> 5;
    const int j0 = jblk * 16;
    const int b0 = bblk * 16;

    // Wh slice (rows 512..1023 of W, cols j0..j0+15), loaded once
    #pragma unroll
    for (int i = 0; i < 8; i++) {
        int idx = tid + i * NTHR2;
        int r = idx >> 2, q = (idx & 3) * 4;
        *(float4*)&ws[r * 16 + q] =
            *(const float4*)(W + (size_t)(IN_DIM + r) * RNN_DIM + j0 + q);
    }

    // out[0] tile = broadcast init_hidden
    {
        int b = tid >> 4, j = tid & 15;
        out[(size_t)(b0 + b) * RNN_DIM + j0 + j] = init_hidden[j0 + j];
    }
    // g_hT[0][r][b0..b0+15] = init_hidden[r]  (one CTA per group: jblk==0)
    if (jblk == 0) {
        int kbase = (tid >> 2) * 8;
        int q = (tid & 3) * 4;
        #pragma unroll
        for (int kk = 0; kk < 8; kk++) {
            int k = kbase + kk;
            float v = init_hidden[k];
            *(float4*)&g_hT[0][k * BATCH + b0 + q] = make_float4(v, v, v, v);
        }
    }
    group_arrive(bblk);

    const int kg = tid >> 4;              // 0..15, k = kg + 16*kk (strided)
    const int tt = tid & 15;
    const int bq = (tt >> 2) * 4;         // 0,4,8,12
    const int jq = (tt & 3) * 4;          // 0,4,8,12
    const int fb = tid >> 4;              // epilogue b
    const int fj = tid & 15;              // epilogue j

    // prefetch pre[0] while waiting for h(0) publication
    float pre = g_pre[((size_t)0 * BATCH + b0 + fb) * RNN_DIM + j0 + fj];
    group_wait(bblk, 1ULL);

    for (int t = 0; t < T_STEPS - 1; t++) {
        const float* hsrc = g_hT[t & 1];

        // stage half0 (rows 0..255)
        float4 r0[4];
        #pragma unroll
        for (int i = 0; i < 4; i++) {
            int idx = tid + i * NTHR2;
            int r = idx >> 2, q = (idx & 3) * 4;
            r0[i] = *(const float4*)(hsrc + r * BATCH + b0 + q);
        }
        #pragma unroll
        for (int i = 0; i < 4; i++) {
            int idx = tid + i * NTHR2;
            int r = idx >> 2, q = (idx & 3) * 4;
            *(float4*)&hs[r * 16 + q] = r0[i];
        }
        __syncthreads();

        // issue half1 loads (rows 256..511), overlap with compute half0
        float4 r1[4];
        #pragma unroll
        for (int i = 0; i < 4; i++) {
            int idx = tid + (i + 4) * NTHR2;
            int r = idx >> 2, q = (idx & 3) * 4;
            r1[i] = *(const float4*)(hsrc + r * BATCH + b0 + q);
        }

        float c[4][4];
        #pragma unroll
        for (int i = 0; i < 4; i++)
            #pragma unroll
            for (int j = 0; j < 4; j++)
                c[i][j] = 0.0f;

        #pragma unroll 4
        for (int kk = 0; kk < 16; kk++) {       // k in [0,256)
            int k = kg + (kk << 4);
            float4 hv = *(float4*)&hs[k * 16 + bq];
            float4 wv = *(float4*)&ws[k * 16 + jq];
            c[0][0] += hv.x * wv.x; c[0][1] += hv.x * wv.y;
            c[0][2] += hv.x * wv.z; c[0][3] += hv.x * wv.w;
            c[1][0] += hv.y * wv.x; c[1][1] += hv.y * wv.y;
            c[1][2] += hv.y * wv.z; c[1][3] += hv.y * wv.w;
            c[2][0] += hv.z * wv.x; c[2][1] += hv.z * wv.y;
            c[2][2] += hv.z * wv.z; c[2][3] += hv.z * wv.w;
            c[3][0] += hv.w * wv.x; c[3][1] += hv.w * wv.y;
            c[3][2] += hv.w * wv.z; c[3][3] += hv.w * wv.w;
        }

        #pragma unroll
        for (int i = 0; i < 4; i++) {
            int idx = tid + (i + 4) * NTHR2;
            int r = idx >> 2, q = (idx & 3) * 4;
            *(float4*)&hs[r * 16 + q] = r1[i];
        }
        __syncthreads();

        #pragma unroll 4
        for (int kk = 16; kk < 32; kk++) {      // k in [256,512)
            int k = kg + (kk << 4);
            float4 hv = *(float4*)&hs[k * 16 + bq];
            float4 wv = *(float4*)&ws[k * 16 + jq];
            c[0][0] += hv.x * wv.x; c[0][1] += hv.x * wv.y;
            c[0][2] += hv.x * wv.z; c[0][3] += hv.x * wv.w;
            c[1][0] += hv.y * wv.x; c[1][1] += hv.y * wv.y;
            c[1][2] += hv.y * wv.z; c[1][3] += hv.y * wv.w;
            c[2][0] += hv.z * wv.x; c[2][1] += hv.z * wv.y;
            c[2][2] += hv.z * wv.z; c[2][3] += hv.z * wv.w;
            c[3][0] += hv.w * wv.x; c[3][1] += hv.w * wv.y;
            c[3][2] += hv.w * wv.z; c[3][3] += hv.w * wv.w;
        }

        // k-split partials overlay hs rows < 256 (safe: half1 reads rows >= 256)
        float* red = hs;
        #pragma unroll
        for (int i = 0; i < 4; i++)
            #pragma unroll
            for (int j = 0; j < 4; j++)
                red[kg * 256 + (bq + i) * 16 + (jq + j)] = c[i][j];
        __syncthreads();

        float s = 0.0f;
        #pragma unroll
        for (int g = 0; g < 16; g++)
            s += red[g * 256 + tid];            // tid == b*16+j, conflict-free
        float h = tanhf(s + pre);
        g_hT[(t + 1) & 1][(j0 + fj) * BATCH + b0 + fb] = h;

        if (t < T_STEPS - 2) {
            group_arrive(bblk);                 // publish ASAP
            // off-critical-path work under the barrier wait:
            out[((size_t)(t + 1) * BATCH + b0 + fb) * RNN_DIM + j0 + fj] = h;
            pre = g_pre[((size_t)(t + 1) * BATCH + b0 + fb) * RNN_DIM + j0 + fj];
            group_wait(bblk, (ull)(t + 2));
        } else {
            out[((size_t)(t + 1) * BATCH + b0 + fb) * RNN_DIM + j0 + fj] = h;
        }
    }
}

// ---------------------------------------------------------------------------
extern "C" void kernel_launch(void* const* d_in, const int* in_sizes, int n_in,
                              void* d_out, int out_size)
{
    const float* X    = (const float*)d_in[0];  // [T, B, IN_DIM]
    const float* W    = (const float*)d_in[1];  // [IN_DIM + RNN_DIM, RNN_DIM]
    const float* bias = (const float*)d_in[2];  // [RNN_DIM]
    const float* h0   = (const float*)d_in[3];  // [RNN_DIM]
    float* out = (float*)d_out;                 // [T, B, RNN_DIM]

    cudaFuncSetAttribute(rnn_seq_kernel,
                         cudaFuncAttributeMaxDynamicSharedMemorySize, 65536);

    dim3 g1((T_STEPS * BATCH) / BM, RNN_DIM / BN);  // (256, 4)
    gemm_pre_kernel<<<g1, 256>>>(X, W, bias);

    rnn_seq_kernel<<<NCTA2, NTHR2, 65536>>>(W, h0, out);
}

// round 12
// speedup vs baseline: 1.1056x; 1.1056x over previous
#include <cuda_runtime.h>
#include <cuda_bf16.h>
#include <math.h>

#define T_STEPS 512
#define BATCH   64
#define IN_DIM  512
#define RNN_DIM 512

#define NCTA2   128   // 32 jblk x 4 bblk
#define NTHR2   256
#define GRP_SZ  32

typedef unsigned long long ull;
typedef unsigned int u32;

// scratch (no device allocs allowed)
__device__ float g_pre[(size_t)T_STEPS * BATCH * RNN_DIM];   // 64MB
__device__ float g_hT[2][RNN_DIM * BATCH];                    // [parity][r][b]
__device__ ull g_grp[4 * 16];                                 // group ctrs, 128B apart

extern __shared__ float smem_dyn[];

// ---------------------------------------------------------------------------
// Phase 1: pre = X @ Wx + bias via bf16-split tensor-core GEMM.
//   x = hi + lo (each bf16);  x*w ~= xh*wh + xl*wh + xh*wl  (drop lo*lo ~2^-18)
// Tile 128x128 per CTA, K-chunks of 64, mma.sync.m16n8k16 (fp32 accum).
// smem rows padded to 136 bf16 (68 u32 == 4 mod 32 -> conflict-free frags).
// Block (0,0) resets phase-2 barrier state (stream-ordered -> race-free).
// ---------------------------------------------------------------------------
#define GBM 128
#define GBN 128
#define GKC 64
#define SROW 136          // bf16 elems per smem row (cols 0..63 hi, 64..127 lo)
#define GSM_BYTES (2 * 128 * SROW * 2)   // A + B planes, 69632 B

__device__ __forceinline__ void split_bf16(float x, __nv_bfloat16& h, __nv_bfloat16& l) {
    h = __float2bfloat16(x);
    l = __float2bfloat16(x - __bfloat162float(h));
}

__device__ __forceinline__ void mma_bf16(float c[4], const u32 a[4], const u32 b[2]) {
    asm volatile(
        "mma.sync.aligned.m16n8k16.row.col.f32.bf16.bf16.f32 "
        "{%0,%1,%2,%3}, {%4,%5,%6,%7}, {%8,%9}, {%0,%1,%2,%3};"
        : "+f"(c[0]), "+f"(c[1]), "+f"(c[2]), "+f"(c[3])
        : "r"(a[0]), "r"(a[1]), "r"(a[2]), "r"(a[3]), "r"(b[0]), "r"(b[1]));
}

__global__ __launch_bounds__(256) void gemm_pre_kernel(
    const float* __restrict__ X,
    const float* __restrict__ W,
    const float* __restrict__ bias)
{
    if (blockIdx.x == 0 && blockIdx.y == 0 && threadIdx.x < 4)
        g_grp[threadIdx.x * 16] = 0ULL;

    __nv_bfloat16* sA = (__nv_bfloat16*)smem_dyn;            // [128 m][SROW]
    __nv_bfloat16* sB = sA + 128 * SROW;                     // [128 n][SROW]

    const int tid  = threadIdx.x;
    const int lane = tid & 31;
    const int wid  = tid >> 5;
    const int bm   = blockIdx.x;    // 256 tiles over M=32768
    const int bn   = blockIdx.y;    // 4 tiles over N=512

    const int warp_m = wid & 1;     // 2 x 4 warp grid -> warp tile 64m x 32n
    const int warp_n = wid >> 1;
    const int g   = lane >> 2;      // 0..7
    const int tig = lane & 3;       // 0..3

    const float* Aptr = X + (size_t)bm * GBM * IN_DIM;

    float c[4][4][4];               // [mi][ni][frag]
    #pragma unroll
    for (int mi = 0; mi < 4; mi++)
        #pragma unroll
        for (int ni = 0; ni < 4; ni++)
            #pragma unroll
            for (int r = 0; r < 4; r++)
                c[mi][ni][r] = 0.0f;

    for (int kc = 0; kc < IN_DIM / GKC; kc++) {
        // ---- stage X chunk [128 m][64 k] as hi|lo (float4 reads) ----
        #pragma unroll
        for (int t = 0; t < 8; t++) {
            int e = tid + t * 256;            // 2048 float4 granules
            int row = e >> 4;
            int kq  = (e & 15) * 4;
            float4 v = *(const float4*)(Aptr + (size_t)row * IN_DIM + kc * GKC + kq);
            __nv_bfloat16 h0, h1, h2, h3, l0, l1, l2, l3;
            split_bf16(v.x, h0, l0); split_bf16(v.y, h1, l1);
            split_bf16(v.z, h2, l2); split_bf16(v.w, h3, l3);
            __nv_bfloat162* pH = (__nv_bfloat162*)&sA[row * SROW + kq];
            pH[0] = __halves2bfloat162(h0, h1);
            pH[1] = __halves2bfloat162(h2, h3);
            __nv_bfloat162* pL = (__nv_bfloat162*)&sA[row * SROW + 64 + kq];
            pL[0] = __halves2bfloat162(l0, l1);
            pL[1] = __halves2bfloat162(l2, l3);
        }
        // ---- stage W chunk [64 k][128 n] transposed -> sB[n][k] hi|lo ----
        #pragma unroll
        for (int t = 0; t < 32; t++) {
            int e = tid + t * 256;            // 8192 scalars
            int k = e >> 7;
            int n = e & 127;
            float v = W[(size_t)(kc * GKC + k) * RNN_DIM + bn * GBN + n];
            __nv_bfloat16 h, l;
            split_bf16(v, h, l);
            sB[n * SROW + k]      = h;
            sB[n * SROW + 64 + k] = l;
        }
        __syncthreads();

        // ---- 3 operand passes: (Ahi,Bhi), (Alo,Bhi), (Ahi,Blo) ----
        #pragma unroll
        for (int p = 0; p < 3; p++) {
            const int offA = (p == 1) ? 64 : 0;
            const int offB = (p == 2) ? 64 : 0;
            #pragma unroll
            for (int k16 = 0; k16 < 4; k16++) {
                const int ka = offA + k16 * 16 + 2 * tig;
                const int kb = offB + k16 * 16 + 2 * tig;
                u32 a[4][4];
                #pragma unroll
                for (int mi = 0; mi < 4; mi++) {
                    int r0 = warp_m * 64 + mi * 16 + g;
                    a[mi][0] = *(const u32*)&sA[(r0    ) * SROW + ka];
                    a[mi][1] = *(const u32*)&sA[(r0 + 8) * SROW + ka];
                    a[mi][2] = *(const u32*)&sA[(r0    ) * SROW + ka + 8];
                    a[mi][3] = *(const u32*)&sA[(r0 + 8) * SROW + ka + 8];
                }
                u32 b[4][2];
                #pragma unroll
                for (int ni = 0; ni < 4; ni++) {
                    int n0 = warp_n * 32 + ni * 8 + g;
                    b[ni][0] = *(const u32*)&sB[n0 * SROW + kb];
                    b[ni][1] = *(const u32*)&sB[n0 * SROW + kb + 8];
                }
                #pragma unroll
                for (int mi = 0; mi < 4; mi++)
                    #pragma unroll
                    for (int ni = 0; ni < 4; ni++)
                        mma_bf16(c[mi][ni], a[mi], b[ni]);
            }
        }
        __syncthreads();   // before next chunk overwrites smem
    }

    // ---- epilogue: + bias, write g_pre ----
    #pragma unroll
    for (int mi = 0; mi < 4; mi++) {
        #pragma unroll
        for (int ni = 0; ni < 4; ni++) {
            int row = bm * GBM + warp_m * 64 + mi * 16 + g;
            int col = bn * GBN + warp_n * 32 + ni * 8 + 2 * tig;
            float b0 = bias[col], b1 = bias[col + 1];
            float2 v0 = make_float2(c[mi][ni][0] + b0, c[mi][ni][1] + b1);
            float2 v1 = make_float2(c[mi][ni][2] + b0, c[mi][ni][3] + b1);
            *(float2*)(g_pre + (size_t)row * RNN_DIM + col)       = v0;
            *(float2*)(g_pre + (size_t)(row + 8) * RNN_DIM + col) = v1;
        }
    }
}

// ---------------------------------------------------------------------------
// Phase 2: persistent RNN — R10 version byte-for-byte (best-equal).
// ---------------------------------------------------------------------------
__device__ __forceinline__ void group_arrive(int grp)
{
    __syncthreads();                     // all g_hT stores issued
    if (threadIdx.x == 0) {
        __threadfence();
        atomicAdd(&g_grp[grp * 16], 1ULL);   // no-return -> REDG
    }
}
__device__ __forceinline__ void group_wait(int grp, ull step)
{
    if (threadIdx.x == 0) {
        volatile ull* ctr = (volatile ull*)&g_grp[grp * 16];
        ull need = (ull)GRP_SZ * step;
        while (*ctr < need) { }
        __threadfence();
    }
    __syncthreads();
}

__global__ __launch_bounds__(NTHR2) void rnn_seq_kernel(
    const float* __restrict__ W,
    const float* __restrict__ init_hidden,
    float* __restrict__ out)
{
    float* ws = smem_dyn;                 // [512][16] Wh slice, 32KB
    float* hs = smem_dyn + RNN_DIM * 16;  // [512][16] h slab, 32KB (rows<256 = red)

    const int tid  = threadIdx.x;
    const int jblk = blockIdx.x & 31;
    const int bblk = blockIdx.x >> 5;
    const int j0 = jblk * 16;
    const int b0 = bblk * 16;

    #pragma unroll
    for (int i = 0; i < 8; i++) {
        int idx = tid + i * NTHR2;
        int r = idx >> 2, q = (idx & 3) * 4;
        *(float4*)&ws[r * 16 + q] =
            *(const float4*)(W + (size_t)(IN_DIM + r) * RNN_DIM + j0 + q);
    }

    {
        int b = tid >> 4, j = tid & 15;
        out[(size_t)(b0 + b) * RNN_DIM + j0 + j] = init_hidden[j0 + j];
    }
    if (jblk == 0) {
        int kbase = (tid >> 2) * 8;
        int q = (tid & 3) * 4;
        #pragma unroll
        for (int kk = 0; kk < 8; kk++) {
            int k = kbase + kk;
            float v = init_hidden[k];
            *(float4*)&g_hT[0][k * BATCH + b0 + q] = make_float4(v, v, v, v);
        }
    }
    group_arrive(bblk);

    const int kg = tid >> 4;
    const int tt = tid & 15;
    const int bq = (tt >> 2) * 4;
    const int jq = (tt & 3) * 4;
    const int fb = tid >> 4;
    const int fj = tid & 15;

    float pre = g_pre[((size_t)0 * BATCH + b0 + fb) * RNN_DIM + j0 + fj];
    group_wait(bblk, 1ULL);

    for (int t = 0; t < T_STEPS - 1; t++) {
        const float* hsrc = g_hT[t & 1];

        float4 r0[4];
        #pragma unroll
        for (int i = 0; i < 4; i++) {
            int idx = tid + i * NTHR2;
            int r = idx >> 2, q = (idx & 3) * 4;
            r0[i] = *(const float4*)(hsrc + r * BATCH + b0 + q);
        }
        #pragma unroll
        for (int i = 0; i < 4; i++) {
            int idx = tid + i * NTHR2;
            int r = idx >> 2, q = (idx & 3) * 4;
            *(float4*)&hs[r * 16 + q] = r0[i];
        }
        __syncthreads();

        float4 r1[4];
        #pragma unroll
        for (int i = 0; i < 4; i++) {
            int idx = tid + (i + 4) * NTHR2;
            int r = idx >> 2, q = (idx & 3) * 4;
            r1[i] = *(const float4*)(hsrc + r * BATCH + b0 + q);
        }

        float c[4][4];
        #pragma unroll
        for (int i = 0; i < 4; i++)
            #pragma unroll
            for (int j = 0; j < 4; j++)
                c[i][j] = 0.0f;

        #pragma unroll 4
        for (int kk = 0; kk < 16; kk++) {
            int k = kg + (kk << 4);
            float4 hv = *(float4*)&hs[k * 16 + bq];
            float4 wv = *(float4*)&ws[k * 16 + jq];
            c[0][0] += hv.x * wv.x; c[0][1] += hv.x * wv.y;
            c[0][2] += hv.x * wv.z; c[0][3] += hv.x * wv.w;
            c[1][0] += hv.y * wv.x; c[1][1] += hv.y * wv.y;
            c[1][2] += hv.y * wv.z; c[1][3] += hv.y * wv.w;
            c[2][0] += hv.z * wv.x; c[2][1] += hv.z * wv.y;
            c[2][2] += hv.z * wv.z; c[2][3] += hv.z * wv.w;
            c[3][0] += hv.w * wv.x; c[3][1] += hv.w * wv.y;
            c[3][2] += hv.w * wv.z; c[3][3] += hv.w * wv.w;
        }

        #pragma unroll
        for (int i = 0; i < 4; i++) {
            int idx = tid + (i + 4) * NTHR2;
            int r = idx >> 2, q = (idx & 3) * 4;
            *(float4*)&hs[r * 16 + q] = r1[i];
        }
        __syncthreads();

        #pragma unroll 4
        for (int kk = 16; kk < 32; kk++) {
            int k = kg + (kk << 4);
            float4 hv = *(float4*)&hs[k * 16 + bq];
            float4 wv = *(float4*)&ws[k * 16 + jq];
            c[0][0] += hv.x * wv.x; c[0][1] += hv.x * wv.y;
            c[0][2] += hv.x * wv.z; c[0][3] += hv.x * wv.w;
            c[1][0] += hv.y * wv.x; c[1][1] += hv.y * wv.y;
            c[1][2] += hv.y * wv.z; c[1][3] += hv.y * wv.w;
            c[2][0] += hv.z * wv.x; c[2][1] += hv.z * wv.y;
            c[2][2] += hv.z * wv.z; c[2][3] += hv.z * wv.w;
            c[3][0] += hv.w * wv.x; c[3][1] += hv.w * wv.y;
            c[3][2] += hv.w * wv.z; c[3][3] += hv.w * wv.w;
        }

        float* red = hs;
        #pragma unroll
        for (int i = 0; i < 4; i++)
            #pragma unroll
            for (int j = 0; j < 4; j++)
                red[kg * 256 + (bq + i) * 16 + (jq + j)] = c[i][j];
        __syncthreads();

        float s = 0.0f;
        #pragma unroll
        for (int gg = 0; gg < 16; gg++)
            s += red[gg * 256 + tid];
        float h = tanhf(s + pre);
        g_hT[(t + 1) & 1][(j0 + fj) * BATCH + b0 + fb] = h;

        if (t < T_STEPS - 2) {
            group_arrive(bblk);
            out[((size_t)(t + 1) * BATCH + b0 + fb) * RNN_DIM + j0 + fj] = h;
            pre = g_pre[((size_t)(t + 1) * BATCH + b0 + fb) * RNN_DIM + j0 + fj];
            group_wait(bblk, (ull)(t + 2));
        } else {
            out[((size_t)(t + 1) * BATCH + b0 + fb) * RNN_DIM + j0 + fj] = h;
        }
    }
}

// ---------------------------------------------------------------------------
extern "C" void kernel_launch(void* const* d_in, const int* in_sizes, int n_in,
                              void* d_out, int out_size)
{
    const float* X    = (const float*)d_in[0];  // [T, B, IN_DIM]
    const float* W    = (const float*)d_in[1];  // [IN_DIM + RNN_DIM, RNN_DIM]
    const float* bias = (const float*)d_in[2];  // [RNN_DIM]
    const float* h0   = (const float*)d_in[3];  // [RNN_DIM]
    float* out = (float*)d_out;                 // [T, B, RNN_DIM]

    cudaFuncSetAttribute(gemm_pre_kernel,
                         cudaFuncAttributeMaxDynamicSharedMemorySize, GSM_BYTES);
    cudaFuncSetAttribute(rnn_seq_kernel,
                         cudaFuncAttributeMaxDynamicSharedMemorySize, 65536);

    dim3 g1((T_STEPS * BATCH) / GBM, RNN_DIM / GBN);  // (256, 4)
    gemm_pre_kernel<<<g1, 256, GSM_BYTES>>>(X, W, bias);

    rnn_seq_kernel<<<NCTA2, NTHR2, 65536>>>(W, h0, out);
}